// round 16
// baseline (speedup 1.0000x reference)
#include <cuda_runtime.h>

// LRN, all-ones cross-channel 5x5 filter — L2-blocked chunked pipeline.
// Batch is processed in 4 chunks of 4 images (x-chunk = 77 MB < 126 MB L2):
//   A(c): s = sum_ch x^2 for chunk c   (reads x-chunk from DRAM -> L2 resident)
//   B(c): f = (2+1e-4*box5x5(s))^-.75 inline; out = x * f
//         (x re-read hits L2; __ldcs/__stcs keep the cache clean for chunk c+1)
// All launches chained with PDL so A(c+1) DRAM reads overlap B(c) L2 drain.

#define Bn 16
#define Cn 96
#define Hn 224
#define Wn 224
#define HWn (Hn * Wn)          // 50176
#define HWq (HWn / 4)          // 12544 quads per channel-plane
#define WQ (Wn / 4)            // 56 quads per row

#define CHUNK_IMGS 4
#define NCHUNKS (Bn / CHUNK_IMGS)            // 4
#define CQUADS (CHUNK_IMGS * HWq)            // 50176 quads per chunk

__device__ float g_smap[Bn * HWn];   // channel-summed squares (3.2 MB)

// ---------------------------------------------------------------------------
// Kernel A: s = sum_c x^2 for one 4-image chunk. One thread per pixel-quad.
// Default load policy: keep x lines resident in L2 for kernel B.
// ---------------------------------------------------------------------------
#define ATHREADS 256

__global__ __launch_bounds__(ATHREADS)
void lrn_ssq_kernel(const float* __restrict__ x, int b0) {
    const int t = blockIdx.x * ATHREADS + threadIdx.x;   // 0 .. CQUADS-1
    const int bl = t / HWq;
    const int q  = t - bl * HWq;
    const int b  = b0 + bl;

    const float4* __restrict__ xp = (const float4*)x + (size_t)b * Cn * HWq + q;

    float4 a = make_float4(0.f, 0.f, 0.f, 0.f);
#pragma unroll
    for (int c0 = 0; c0 < Cn; c0 += 8) {
        float4 v[8];
#pragma unroll
        for (int k = 0; k < 8; k++)
            v[k] = __ldg(xp + (c0 + k) * HWq);           // resident: B re-reads
#pragma unroll
        for (int k = 0; k < 8; k++) {
            a.x = fmaf(v[k].x, v[k].x, a.x);
            a.y = fmaf(v[k].y, v[k].y, a.y);
            a.z = fmaf(v[k].z, v[k].z, a.z);
            a.w = fmaf(v[k].w, v[k].w, a.w);
        }
    }
    ((float4*)g_smap)[(size_t)b * HWq + q] = a;

    cudaTriggerProgrammaticLaunchCompletion();
}

// ---------------------------------------------------------------------------
// Kernel B: inline box5x5(s) + pow, then out = x * f for one chunk.
// x reads should hit L2 (chunk just loaded by A). __ldcs: line dead after use.
// ---------------------------------------------------------------------------
#define BTHREADS 256

__global__ __launch_bounds__(BTHREADS)
void lrn_scale_kernel(const float* __restrict__ x, float* __restrict__ out,
                      int b0) {
    const int t = blockIdx.x * BTHREADS + threadIdx.x;
    const int bl = t / HWq;
    const int q  = t - bl * HWq;
    const int b  = b0 + bl;
    const int r  = q / WQ;          // pixel row 0..223
    const int jq = q - r * WQ;      // quad column 0..55

    // ---- wait for this chunk's g_smap writes (kernel A) to be visible
    cudaGridDependencySynchronize();

    // ---- vertical sum of s over rows r-2..r+2, 12 columns [4*jq-4, 4*jq+8)
    float vs[12];
#pragma unroll
    for (int k = 0; k < 12; k++) vs[k] = 0.0f;

    const float4* __restrict__ s4 = (const float4*)g_smap;
#pragma unroll
    for (int dh = -2; dh <= 2; dh++) {
        const int h2 = r + dh;
        if ((unsigned)h2 < (unsigned)Hn) {
            const int rowq = (b * HWn + h2 * Wn) >> 2;
#pragma unroll
            for (int tq = 0; tq < 3; tq++) {
                const int qi = jq - 1 + tq;
                if ((unsigned)qi < (unsigned)WQ) {
                    const float4 v = __ldg(s4 + rowq + qi);
                    vs[tq * 4 + 0] += v.x;
                    vs[tq * 4 + 1] += v.y;
                    vs[tq * 4 + 2] += v.z;
                    vs[tq * 4 + 3] += v.w;
                }
            }
        }
    }

    // ---- horizontal 5-tap sums + fast pow: pixel p needs vs[2+p .. 6+p]
    float4 f;
    {
        float y0 = vs[2] + vs[3] + vs[4] + vs[5] + vs[6];
        float y1 = vs[3] + vs[4] + vs[5] + vs[6] + vs[7];
        float y2 = vs[4] + vs[5] + vs[6] + vs[7] + vs[8];
        float y3 = vs[5] + vs[6] + vs[7] + vs[8] + vs[9];
        f.x = __powf(fmaf(1e-4f, y0, 2.0f), -0.75f);   // base >= 2: fast-log safe
        f.y = __powf(fmaf(1e-4f, y1, 2.0f), -0.75f);
        f.z = __powf(fmaf(1e-4f, y2, 2.0f), -0.75f);
        f.w = __powf(fmaf(1e-4f, y3, 2.0f), -0.75f);
    }

    // Allow the next chunk's A to start queueing (overlaps our L2 drain).
    cudaTriggerProgrammaticLaunchCompletion();

    // ---- main stream: out = x * f over 96 channels (x from L2)
    const float4* __restrict__ xp = (const float4*)x + (size_t)b * Cn * HWq + q;
    float4* __restrict__ op = (float4*)out + (size_t)b * Cn * HWq + q;

#pragma unroll
    for (int c0 = 0; c0 < Cn; c0 += 8) {
        float4 v[8];
#pragma unroll
        for (int k = 0; k < 8; k++)
            v[k] = __ldcs(xp + (c0 + k) * HWq);      // read-once: evict-first
#pragma unroll
        for (int k = 0; k < 8; k++) {
            v[k].x *= f.x; v[k].y *= f.y; v[k].z *= f.z; v[k].w *= f.w;
            __stcs(op + (c0 + k) * HWq, v[k]);       // never re-read
        }
    }
}

extern "C" void kernel_launch(void* const* d_in, const int* in_sizes, int n_in,
                              void* d_out, int out_size) {
    const float* x = (const float*)d_in[0];
    float* out = (float*)d_out;

    cudaLaunchAttribute attrs[1];
    attrs[0].id = cudaLaunchAttributeProgrammaticStreamSerialization;
    attrs[0].val.programmaticStreamSerializationAllowed = 1;

    for (int c = 0; c < NCHUNKS; c++) {
        const int b0 = c * CHUNK_IMGS;

        cudaLaunchConfig_t cfgA = {};
        cfgA.gridDim  = dim3(CQUADS / ATHREADS, 1, 1);   // 196 blocks
        cfgA.blockDim = dim3(ATHREADS, 1, 1);
        cfgA.stream = 0;
        cfgA.attrs = attrs;
        cfgA.numAttrs = 1;
        cudaLaunchKernelEx(&cfgA, lrn_ssq_kernel, x, b0);

        cudaLaunchConfig_t cfgB = {};
        cfgB.gridDim  = dim3(CQUADS / BTHREADS, 1, 1);   // 196 blocks
        cfgB.blockDim = dim3(BTHREADS, 1, 1);
        cfgB.stream = 0;
        cfgB.attrs = attrs;
        cfgB.numAttrs = 1;
        cudaLaunchKernelEx(&cfgB, lrn_scale_kernel, x, out, b0);
    }
}

// round 17
// speedup vs baseline: 1.1000x; 1.1000x over previous
#include <cuda_runtime.h>

// LRN, all-ones cross-channel 5x5 filter — L2-blocked chunks, full parallelism.
// 4 chunks of 4 images (77 MB x-chunk < 126 MB L2). Per chunk:
//   A : 4-way channel-split partial ssq (784 blocks) -> g_part[4]
//   A2: sum partials + 5x5 box + pow -> g_fmap (tiled smem, tiny)
//   B : out = x * f, 4-way channel-split (784 blocks); x re-reads hit L2.
// PDL chains all launches; chunk-indexed buffers keep overlap race-free.

#define Bn 16
#define Cn 96
#define Hn 224
#define Wn 224
#define HWn (Hn * Wn)          // 50176
#define HWq (HWn / 4)          // 12544 quads per channel-plane
#define WQ (Wn / 4)            // 56 quads per row

#define CHUNK_IMGS 4
#define NCHUNKS (Bn / CHUNK_IMGS)            // 4
#define CQUADS (CHUNK_IMGS * HWq)            // 50176 quads per chunk
#define NGRP 4
#define CG (Cn / NGRP)                       // 24 channels per group

__device__ float g_part[NGRP][Bn * HWn];     // partial ssq maps (12.8 MB)
__device__ float g_fmap[Bn * HWn];           // scale-factor map  (3.2 MB)

// ---------------------------------------------------------------------------
// Kernel A: partial ssq over 24 channels. 4 groups x 50176 quads per chunk.
// ---------------------------------------------------------------------------
#define ATHREADS 256

__global__ __launch_bounds__(ATHREADS)
void lrn_ssq_kernel(const float* __restrict__ x, int b0) {
    const int t   = blockIdx.x * ATHREADS + threadIdx.x;  // 0 .. 4*CQUADS-1
    const int g   = t / CQUADS;
    const int rem = t - g * CQUADS;
    const int bl  = rem / HWq;
    const int q   = rem - bl * HWq;
    const int b   = b0 + bl;

    const float4* __restrict__ xp = (const float4*)x
        + (size_t)b * Cn * HWq + (size_t)g * CG * HWq + q;

    float4 a = make_float4(0.f, 0.f, 0.f, 0.f);
#pragma unroll
    for (int c0 = 0; c0 < CG; c0 += 8) {
        float4 v[8];
#pragma unroll
        for (int k = 0; k < 8; k++)
            v[k] = __ldg(xp + (c0 + k) * HWq);           // keep resident for B
#pragma unroll
        for (int k = 0; k < 8; k++) {
            a.x = fmaf(v[k].x, v[k].x, a.x);
            a.y = fmaf(v[k].y, v[k].y, a.y);
            a.z = fmaf(v[k].z, v[k].z, a.z);
            a.w = fmaf(v[k].w, v[k].w, a.w);
        }
    }
    ((float4*)g_part[g])[(size_t)b * HWq + q] = a;

    cudaTriggerProgrammaticLaunchCompletion();
}

// ---------------------------------------------------------------------------
// Kernel A2: s = sum of 4 partials; f = (2 + 1e-4*box5x5(s))^(-0.75).
// Tiled 32x32, halo in smem. Partials are L2-hot. Tiny kernel.
// ---------------------------------------------------------------------------
#define TILE 32
#define SROWS (TILE + 4)       // 36
#define SQ 10                  // quads per halo row
#define NQ (SROWS * SQ)        // 360
#define SCOLS (SQ * 4)         // 40
#define A2THREADS 384

__global__ __launch_bounds__(A2THREADS)
void lrn_fmap_kernel(int b0) {
    __shared__ float s_s[SROWS * SCOLS];

    const int tid = threadIdx.x;
    const int b   = b0 + blockIdx.z;
    const int h0  = blockIdx.y * TILE;
    const int w0  = blockIdx.x * TILE;

    cudaGridDependencySynchronize();   // wait for this chunk's A partials

    if (tid < NQ) {
        const int sr = tid / SQ;
        const int sq = tid - sr * SQ;
        const int gh = h0 - 2 + sr;
        const int gw = w0 - 4 + sq * 4;     // quad fully in or out
        float4 s = make_float4(0.f, 0.f, 0.f, 0.f);
        if (((unsigned)gh < (unsigned)Hn) && ((unsigned)gw < (unsigned)Wn)) {
            const int qi = (b * HWn + gh * Wn + gw) >> 2;
#pragma unroll
            for (int g = 0; g < NGRP; g++) {
                const float4 v = __ldg((const float4*)g_part[g] + qi);
                s.x += v.x; s.y += v.y; s.z += v.z; s.w += v.w;
            }
        }
        ((float4*)s_s)[tid] = s;
    }
    __syncthreads();

#pragma unroll
    for (int p = tid; p < TILE * TILE; p += A2THREADS) {
        const int i = p >> 5;
        const int j = p & 31;
        float sum = 0.0f;
#pragma unroll
        for (int di = 0; di < 5; di++) {
#pragma unroll
            for (int dj = 0; dj < 5; dj++) {
                sum += s_s[(i + di) * SCOLS + (j + 2 + dj)];
            }
        }
        const float bse = fmaf(1e-4f, sum, 2.0f);   // >= 2, fast-log safe
        g_fmap[b * HWn + (h0 + i) * Wn + (w0 + j)] = __powf(bse, -0.75f);
    }

    cudaTriggerProgrammaticLaunchCompletion();
}

// ---------------------------------------------------------------------------
// Kernel B: out = x * f over 24 channels per thread (4 groups). x from L2.
// ---------------------------------------------------------------------------
#define BTHREADS 256

__global__ __launch_bounds__(BTHREADS)
void lrn_scale_kernel(const float* __restrict__ x, float* __restrict__ out,
                      int b0) {
    const int t   = blockIdx.x * BTHREADS + threadIdx.x;
    const int g   = t / CQUADS;
    const int rem = t - g * CQUADS;
    const int bl  = rem / HWq;
    const int q   = rem - bl * HWq;
    const int b   = b0 + bl;

    cudaGridDependencySynchronize();   // wait for this chunk's f map

    const float4 f = __ldg((const float4*)g_fmap + (size_t)b * HWq + q);

    cudaTriggerProgrammaticLaunchCompletion();   // let next chunk's A queue up

    const size_t base = (size_t)b * Cn * HWq + (size_t)g * CG * HWq + q;
    const float4* __restrict__ xp = (const float4*)x + base;
    float4* __restrict__ op = (float4*)out + base;

#pragma unroll
    for (int c0 = 0; c0 < CG; c0 += 8) {
        float4 v[8];
#pragma unroll
        for (int k = 0; k < 8; k++)
            v[k] = __ldcs(xp + (c0 + k) * HWq);      // read-once: evict-first
#pragma unroll
        for (int k = 0; k < 8; k++) {
            v[k].x *= f.x; v[k].y *= f.y; v[k].z *= f.z; v[k].w *= f.w;
            __stcs(op + (c0 + k) * HWq, v[k]);       // never re-read
        }
    }
}

extern "C" void kernel_launch(void* const* d_in, const int* in_sizes, int n_in,
                              void* d_out, int out_size) {
    const float* x = (const float*)d_in[0];
    float* out = (float*)d_out;

    cudaLaunchAttribute attrs[1];
    attrs[0].id = cudaLaunchAttributeProgrammaticStreamSerialization;
    attrs[0].val.programmaticStreamSerializationAllowed = 1;

    for (int c = 0; c < NCHUNKS; c++) {
        const int b0 = c * CHUNK_IMGS;

        cudaLaunchConfig_t cfgA = {};
        cfgA.gridDim  = dim3(NGRP * CQUADS / ATHREADS, 1, 1);  // 784 blocks
        cfgA.blockDim = dim3(ATHREADS, 1, 1);
        cfgA.stream = 0; cfgA.attrs = attrs; cfgA.numAttrs = 1;
        cudaLaunchKernelEx(&cfgA, lrn_ssq_kernel, x, b0);

        cudaLaunchConfig_t cfgA2 = {};
        cfgA2.gridDim  = dim3(Wn / TILE, Hn / TILE, CHUNK_IMGS); // 7x7x4
        cfgA2.blockDim = dim3(A2THREADS, 1, 1);
        cfgA2.stream = 0; cfgA2.attrs = attrs; cfgA2.numAttrs = 1;
        cudaLaunchKernelEx(&cfgA2, lrn_fmap_kernel, b0);

        cudaLaunchConfig_t cfgB = {};
        cfgB.gridDim  = dim3(NGRP * CQUADS / BTHREADS, 1, 1);  // 784 blocks
        cfgB.blockDim = dim3(BTHREADS, 1, 1);
        cfgB.stream = 0; cfgB.attrs = attrs; cfgB.numAttrs = 1;
        cudaLaunchKernelEx(&cfgB, lrn_scale_kernel, x, out, b0);
    }
}